// round 12
// baseline (speedup 1.0000x reference)
#include <cuda_runtime.h>
#include <math.h>
#include <float.h>
#include <stdint.h>

#define Bb 4
#define Nn 8192
#define Ss 2048
#define Kk 64
#define EPSf 1e-5f

#define FCTAS 4                  // 1 FPS CTA per batch
#define WCTAS 144                // persistent worker CTAs
#define GRID  (FCTAS + WCTAS)    // 148 CTAs = 1/SM, single wave
#define TPB   256
#define NT2   ((Bb*Ss)/2)        // worker tasks (2 centroids each)

typedef unsigned long long ull;

// ---------------- device scratch ----------------
__device__ float g_cen[Bb*Ss*3];
__device__ int   g_prog[Bb];
__device__ float g_sx[Bb*Nn];    // spatially sorted coords
__device__ float g_sy[Bb*Nn];
__device__ float g_sz[Bb*Nn];
__device__ float g_wf1[64*67];
__device__ float g_bf1[64];
__device__ float g_wf2[64*64];
__device__ float g_bf2[64];
__device__ float g_wf3[128*64];
__device__ float g_bf3[128];

// ---------------- packed f32x2 helpers (per-lane rn == scalar rn) ----------------
__device__ __forceinline__ ull pk2(float lo, float hi) {
    ull r; asm("mov.b64 %0, {%1, %2};" : "=l"(r) : "f"(lo), "f"(hi)); return r;
}
__device__ __forceinline__ void up2(ull v, float& a, float& b) {
    asm("mov.b64 {%0, %1}, %2;" : "=f"(a), "=f"(b) : "l"(v));
}
__device__ __forceinline__ ull add2(ull a, ull b) {
    ull r; asm("add.rn.f32x2 %0, %1, %2;" : "=l"(r) : "l"(a), "l"(b)); return r;
}
__device__ __forceinline__ ull mul2(ull a, ull b) {
    ull r; asm("mul.rn.f32x2 %0, %1, %2;" : "=l"(r) : "l"(a), "l"(b)); return r;
}

__device__ __forceinline__ int ld_acquire_gpu(const int* p) {
    int v; asm volatile("ld.acquire.gpu.global.s32 %0, [%1];" : "=r"(v) : "l"(p) : "memory");
    return v;
}
__device__ __forceinline__ void st_release_gpu(int* p, int v) {
    asm volatile("st.release.gpu.global.s32 [%0], %1;" :: "l"(p), "r"(v) : "memory");
}

// ---------------- fold BN into conv + reset progress ----------------
__global__ void fold_kernel(
    const float* W1, const float* b1, const float* g1, const float* bt1, const float* m1, const float* v1,
    const float* W2, const float* b2, const float* g2, const float* bt2, const float* m2, const float* v2,
    const float* W3, const float* b3, const float* g3, const float* bt3, const float* m3, const float* v3)
{
    int t = threadIdx.x;
    for (int i = t; i < 64*67; i += blockDim.x) {
        int o = i / 67;
        g_wf1[i] = W1[i] * (g1[o] * rsqrtf(v1[o] + EPSf));
    }
    for (int i = t; i < 64; i += blockDim.x)
        g_bf1[i] = (b1[i] - m1[i]) * (g1[i] * rsqrtf(v1[i] + EPSf)) + bt1[i];
    for (int i = t; i < 64*64; i += blockDim.x) {
        int o = i >> 6;
        g_wf2[i] = W2[i] * (g2[o] * rsqrtf(v2[o] + EPSf));
    }
    for (int i = t; i < 64; i += blockDim.x)
        g_bf2[i] = (b2[i] - m2[i]) * (g2[i] * rsqrtf(v2[i] + EPSf)) + bt2[i];
    for (int i = t; i < 128*64; i += blockDim.x) {
        int o = i >> 6;
        g_wf3[i] = W3[i] * (g3[o] * rsqrtf(v3[o] + EPSf));
    }
    for (int i = t; i < 128; i += blockDim.x)
        g_bf3[i] = (b3[i] - m3[i]) * (g3[i] * rsqrtf(v3[i] + EPSf)) + bt3[i];

    if (t < Bb) g_prog[t] = 0;
}

// ---------------- spatial counting sort (Morton 8x8x8) ----------------
__global__ void __launch_bounds__(1024) sort_kernel(const float* __restrict__ x)
{
    __shared__ int cnt[512];
    __shared__ int base[512];
    const int b = blockIdx.x;
    const int tid = threadIdx.x;
    const float* xb = x + (size_t)b * Nn * 3;

    if (tid < 512) cnt[tid] = 0;
    __syncthreads();

    int cid[8];
#pragma unroll
    for (int j = 0; j < 8; j++) {
        int p = tid * 8 + j;
        float px = xb[p*3 + 0], py = xb[p*3 + 1], pz = xb[p*3 + 2];
        int ix = min(7, max(0, (int)(px * 8.0f)));
        int iy = min(7, max(0, (int)(py * 8.0f)));
        int iz = min(7, max(0, (int)(pz * 8.0f)));
        int m = (ix & 1) | ((iy & 1) << 1) | ((iz & 1) << 2)
              | ((ix & 2) << 2) | ((iy & 2) << 3) | ((iz & 2) << 4)
              | ((ix & 4) << 4) | ((iy & 4) << 5) | ((iz & 4) << 6);
        cid[j] = m;
        atomicAdd(&cnt[m], 1);
    }
    __syncthreads();
    if (tid == 0) {
        int acc = 0;
        for (int i = 0; i < 512; i++) { base[i] = acc; acc += cnt[i]; }
    }
    __syncthreads();
    if (tid < 512) cnt[tid] = 0;
    __syncthreads();
#pragma unroll
    for (int j = 0; j < 8; j++) {
        int p = tid * 8 + j;
        int pos = base[cid[j]] + atomicAdd(&cnt[cid[j]], 1);
        g_sx[b*Nn + pos] = xb[p*3 + 0];
        g_sy[b*Nn + pos] = xb[p*3 + 1];
        g_sz[b*Nn + pos] = xb[p*3 + 2];
    }
}

// ---------------- shared-memory layout (floats) : worker view ----------------
#define OW1 0
#define OB1 (OW1 + 64*67)
#define OW2 (OB1 + 64)
#define OB2 (OW2 + 64*65)
#define OW3 (OB2 + 64)
#define OB3 (OW3 + 128*65)
#define OBUF (OB3 + 128)
#define GRP  (67*65 + 64*65)
#define OIDXA (OBUF + 2*GRP)
#define SMEM_FLOATS (OIDXA + 2*64)
#define SMEM_BYTES_W ((OIDXA + 2*64) * 4)
// fps view (same dynamic buffer): sorted coords + packed combine slots
#define F_SX   0
#define F_SY   Nn
#define F_SZ   (2*Nn)
#define F_KEY  (3*Nn)            // [2][8] u64 (parity-buffered packed {val,idx})
#define SMEM_BYTES_F ((3*Nn + 32) * 4)
#define SMEM_BYTES (SMEM_BYTES_W > SMEM_BYTES_F ? SMEM_BYTES_W : SMEM_BYTES_F)

// =====================================================================
// persistent kernel, single launch (256 threads everywhere):
//   CTA 0..3   : FPS, 256 thr x 32 pts, exact pruning, 8-warp barrier
//   CTA 4..147 : workers (2 x 128-thread groups), consume via g_prog
// =====================================================================
__global__ void __launch_bounds__(TPB, 1)
pipe_kernel(const float* __restrict__ x, const float* __restrict__ xc,
            float* __restrict__ out)
{
    extern __shared__ float sm[];
    const int tid  = threadIdx.x;
    const int lane = tid & 31;
    const int wrp  = tid >> 5;

    if (blockIdx.x < FCTAS) {
        // ================= FPS (256 threads, 32 sorted pts/thread) =================
        const int b = blockIdx.x;

        float* sxs = sm + F_SX;
        float* sys = sm + F_SY;
        float* szs = sm + F_SZ;
        ull* skeyA = (ull*)(sm + F_KEY);    // [2][8]

        for (int i = tid; i < Nn; i += TPB) {
            sxs[i] = g_sx[b*Nn + i];
            sys[i] = g_sy[b*Nn + i];
            szs[i] = g_sz[b*Nn + i];
        }

        // 32 sorted points per thread (16 packed pairs); static reg indexing only
        ull px[16], py[16], pz[16];
        float dist[32];
#pragma unroll
        for (int i = 0; i < 16; i++) {
            int p = b*Nn + tid * 32 + i * 2;
            px[i] = pk2(g_sx[p], g_sx[p+1]);
            py[i] = pk2(g_sy[p], g_sy[p+1]);
            pz[i] = pk2(g_sz[p], g_sz[p+1]);
        }
#pragma unroll
        for (int j = 0; j < 32; j++) dist[j] = 1e10f;

        // per-thread bounding ball (m, rr) over its 32 points (conservative fp)
        float mx = 0.f, my = 0.f, mz = 0.f;
#pragma unroll
        for (int i = 0; i < 16; i++) {
            float a0, a1;
            up2(px[i], a0, a1); mx += a0 + a1;
            up2(py[i], a0, a1); my += a0 + a1;
            up2(pz[i], a0, a1); mz += a0 + a1;
        }
        mx *= 0.03125f; my *= 0.03125f; mz *= 0.03125f;
        float r2 = 0.f;
#pragma unroll
        for (int i = 0; i < 16; i++) {
            float a0, a1, b0, b1, c0, c1;
            up2(px[i], a0, a1); up2(py[i], b0, b1); up2(pz[i], c0, c1);
            float dx0 = a0 - mx, dy0 = b0 - my, dz0 = c0 - mz;
            float dx1 = a1 - mx, dy1 = b1 - my, dz1 = c1 - mz;
            r2 = fmaxf(r2, dx0*dx0 + dy0*dy0 + dz0*dz0);
            r2 = fmaxf(r2, dx1*dx1 + dy1*dy1 + dz1*dz1);
        }
        const float rr = __fsqrt_rn(r2) * 1.0002f + 1e-7f;

        float T  = 3.0e38f;      // prune threshold (forces full path initially)
        float bv = 0.f;          // cached per-thread max dist
        int   bj = 0;            // cached per-thread best local j (0..31)

        // initial centroid = ORIGINAL point 0's coords
        const float* xb0 = x + (size_t)b * Nn * 3;
        float cx = xb0[0], cy = xb0[1], cz = xb0[2];

        int* progp = &g_prog[b];
        __syncthreads();   // staging done

        for (int s = 0; s < Ss; s++) {
            const int par = s & 1;
            if (tid == 0) {
                int oc = (b*Ss + s) * 3;
                g_cen[oc+0] = cx; g_cen[oc+1] = cy; g_cen[oc+2] = cz;
                out[oc+0]  = cx; out[oc+1]  = cy; out[oc+2]  = cz;
                if ((s & 15) == 15) st_release_gpu(progp, s + 1);
            }

            // exact prune: |c-m| >= rr + sqrt(bv) (with margins) -> no update possible
            float ex = cx - mx, ey = cy - my, ez = cz - mz;
            float s2 = fmaf(ez, ez, fmaf(ey, ey, ex*ex));
            bool fullp = s2 < T;
            if (__any_sync(0xffffffffu, fullp)) {
                if (fullp) {
                    const ull ncx = pk2(-cx, -cx);
                    const ull ncy = pk2(-cy, -cy);
                    const ull ncz = pk2(-cz, -cz);
                    float nbv = -1.0f;
                    int   nbj = 0;
#pragma unroll
                    for (int i = 0; i < 16; i++) {
                        ull dx = add2(px[i], ncx);
                        ull dy = add2(py[i], ncy);
                        ull dz = add2(pz[i], ncz);
                        ull dd = add2(add2(mul2(dx,dx), mul2(dy,dy)), mul2(dz,dz));
                        float d0, d1; up2(dd, d0, d1);
                        float n0 = fminf(dist[2*i],   d0);
                        float n1 = fminf(dist[2*i+1], d1);
                        dist[2*i] = n0; dist[2*i+1] = n1;
                        float vp = fmaxf(n0, n1);
                        int   jp = (n0 >= n1) ? (2*i) : (2*i + 1);  // tie -> lower j
                        if (vp > nbv) { nbv = vp; nbj = jp; }       // strict > keeps lower j
                    }
                    bv = nbv; bj = nbj;
                    float sq = __fsqrt_rn(bv) * 1.0001f;
                    float t0 = (rr + sq) * 1.0001f;
                    T = t0 * t0;
                }
            }

            // warp combine: max value, then min sorted index on ties
            unsigned mv   = __float_as_uint(bv);
            unsigned wmax = __reduce_max_sync(0xffffffffu, mv);
            unsigned cand = (mv == wmax) ? (unsigned)(tid*32 + bj) : 0xffffffffu;
            unsigned wmi  = __reduce_min_sync(0xffffffffu, cand);

            // one packed STS.64 per warp
            if (lane == 0)
                skeyA[par*8 + wrp] = ((ull)wmax << 32) | (ull)wmi;
            __syncthreads();   // single 8-warp barrier per step

            // every warp redundantly reduces the 8 warp results
            ull k = (lane < 8) ? skeyA[par*8 + lane] : 0ull;
            unsigned v  = (unsigned)(k >> 32);
            unsigned id = (lane < 8) ? (unsigned)k : 0xffffffffu;
            unsigned M  = __reduce_max_sync(0xffffffffu, v);
            unsigned cn = (v == M) ? id : 0xffffffffu;
            int cur = (int)__reduce_min_sync(0xffffffffu, cn);   // sorted index
            cx = sxs[cur]; cy = sys[cur]; cz = szs[cur];
        }
        return;
    }

    // ================= persistent worker: ball query + MLP (256 thr) =================
    const int widx_ = blockIdx.x - FCTAS;

    for (int i = tid; i < 64*67; i += TPB) sm[OW1 + i] = g_wf1[i];
    for (int i = tid; i < 64*64; i += TPB) {
        int o = i >> 6, c = i & 63;
        sm[OW2 + o*65 + c] = g_wf2[i];
    }
    for (int i = tid; i < 128*64; i += TPB) {
        int o = i >> 6, c = i & 63;
        sm[OW3 + o*65 + c] = g_wf3[i];
    }
    for (int i = tid; i < 64;  i += TPB) { sm[OB1+i] = g_bf1[i]; sm[OB2+i] = g_bf2[i]; }
    for (int i = tid; i < 128; i += TPB) sm[OB3 + i] = g_bf3[i];

    float* pooled = out + (size_t)Bb * Ss * 3;

    // 2 warpgroups of 128 threads; one centroid per group
    const int wgid    = tid >> 7;        // 0..1
    const int wg_tid  = tid & 127;
    const int tx      = wg_tid & 15;     // 4 k-cols each
    const int ty      = wg_tid >> 4;     // 8 out-rows each (0..7)
    const int wg_warp = (tid >> 5) & 3;

    for (int t = widx_; t < NT2; t += WCTAS) {
        const int b  = t & 3;
        const int s0 = (t >> 2) * 2;

        if (tid == 0) {
            while (ld_acquire_gpu(&g_prog[b]) < s0 + 2) __nanosleep(128);
        }
        __syncthreads();   // progress visible + previous task's buffers free

        // ---- ball query: warps 0..1, one centroid each ----
        if (wrp < 2) {
            const int cen = b * Ss + s0 + wrp;
            const float cx = g_cen[cen*3 + 0];
            const float cy = g_cen[cen*3 + 1];
            const float cz = g_cen[cen*3 + 2];
            const float* xb = x + (size_t)b * Nn * 3;
            int* outp = (int*)&sm[OIDXA + wrp*64];

            int count = 0;
            for (int base = 0; base < Nn && count < Kk; base += 32) {
                int p = base + lane;
                float qx = xb[p*3 + 0], qy = xb[p*3 + 1], qz = xb[p*3 + 2];
                float dx = __fsub_rn(cx, qx);
                float dy = __fsub_rn(cy, qy);
                float dz = __fsub_rn(cz, qz);
                float d  = __fadd_rn(__fadd_rn(__fmul_rn(dx,dx), __fmul_rn(dy,dy)),
                                     __fmul_rn(dz,dz));
                bool hit = d < 0.04f;
                unsigned m = __ballot_sync(0xffffffffu, hit);
                int rk = __popc(m & ((1u << lane) - 1u));
                if (hit && (count + rk) < Kk) outp[count + rk] = p;
                count += __popc(m);
            }
            count = min(count, Kk);
            for (int q = count + lane; q < Kk; q += 32) outp[q] = -1;
        }
        __syncthreads();

        const int cen = b * Ss + s0 + wgid;
        const int OF = OBUF + wgid * GRP;   // F [67][65]
        const int OH = OF + 67*65;          // H [64][65]
        int* sidx = (int*)&sm[OIDXA + wgid*64];

        // ---- gather: 4 warps per group, 16 ks per warp ----
        const float* xcb = xc + (size_t)b * Nn * 64;
        const float* xb  = x  + (size_t)b * Nn * 3;
        for (int kk = 0; kk < 16; kk++) {
            int k  = wg_warp * 16 + kk;
            int gi = sidx[k];
            gi = gi < 0 ? 0 : gi;
            const float* row = xcb + (size_t)gi * 64;
            sm[OF + lane*65 + k]      = row[lane];
            sm[OF + (lane+32)*65 + k] = row[lane + 32];
            if (lane < 3)
                sm[OF + (64+lane)*65 + k] = xb[gi*3 + lane] - g_cen[cen*3 + lane];
        }
        __syncthreads();

        float acc[8][4];

        // ---- layer 1: H = relu(W1f @ F + b1f) ----
#pragma unroll
        for (int i = 0; i < 8; i++)
#pragma unroll
            for (int j = 0; j < 4; j++) acc[i][j] = 0.f;
        for (int c = 0; c < 67; c++) {
            float fv[4];
#pragma unroll
            for (int j = 0; j < 4; j++) fv[j] = sm[OF + c*65 + tx*4 + j];
#pragma unroll
            for (int i = 0; i < 8; i++) {
                float wv = sm[OW1 + (ty*8 + i)*67 + c];
#pragma unroll
                for (int j = 0; j < 4; j++) acc[i][j] = fmaf(wv, fv[j], acc[i][j]);
            }
        }
#pragma unroll
        for (int i = 0; i < 8; i++) {
            float bia = sm[OB1 + ty*8 + i];
#pragma unroll
            for (int j = 0; j < 4; j++)
                sm[OH + (ty*8 + i)*65 + tx*4 + j] = fmaxf(acc[i][j] + bia, 0.f);
        }
        __syncthreads();

        // ---- layer 2 (into F buffer) ----
#pragma unroll
        for (int i = 0; i < 8; i++)
#pragma unroll
            for (int j = 0; j < 4; j++) acc[i][j] = 0.f;
        for (int c = 0; c < 64; c++) {
            float fv[4];
#pragma unroll
            for (int j = 0; j < 4; j++) fv[j] = sm[OH + c*65 + tx*4 + j];
#pragma unroll
            for (int i = 0; i < 8; i++) {
                float wv = sm[OW2 + (ty*8 + i)*65 + c];
#pragma unroll
                for (int j = 0; j < 4; j++) acc[i][j] = fmaf(wv, fv[j], acc[i][j]);
            }
        }
#pragma unroll
        for (int i = 0; i < 8; i++) {
            float bia = sm[OB2 + ty*8 + i];
#pragma unroll
            for (int j = 0; j < 4; j++)
                sm[OF + (ty*8 + i)*65 + tx*4 + j] = fmaxf(acc[i][j] + bia, 0.f);
        }
        __syncthreads();

        // ---- layer 3 (128 outs, two 64-row passes) + masked maxpool ----
        for (int op = 0; op < 2; op++) {
#pragma unroll
            for (int i = 0; i < 8; i++)
#pragma unroll
                for (int j = 0; j < 4; j++) acc[i][j] = 0.f;
            for (int c = 0; c < 64; c++) {
                float fv[4];
#pragma unroll
                for (int j = 0; j < 4; j++) fv[j] = sm[OF + c*65 + tx*4 + j];
#pragma unroll
                for (int i = 0; i < 8; i++) {
                    float wv = sm[OW3 + (op*64 + ty*8 + i)*65 + c];
#pragma unroll
                    for (int j = 0; j < 4; j++) acc[i][j] = fmaf(wv, fv[j], acc[i][j]);
                }
            }
#pragma unroll
            for (int i = 0; i < 8; i++) {
                int o = op*64 + ty*8 + i;
                float bia = sm[OB3 + o];
                float m = -INFINITY;
#pragma unroll
                for (int j = 0; j < 4; j++) {
                    int k = tx*4 + j;
                    float v = fmaxf(acc[i][j] + bia, 0.f);
                    if (sidx[k] >= 0) m = fmaxf(m, v);
                }
                // reduce across the 16 tx threads (contiguous 16-lane groups)
#pragma unroll
                for (int off = 8; off; off >>= 1)
                    m = fmaxf(m, __shfl_xor_sync(0xffffffffu, m, off, 16));
                if (tx == 0) pooled[(size_t)cen * 128 + o] = m;
            }
        }
    }
}

// ---------------- launch ----------------
extern "C" void kernel_launch(void* const* d_in, const int* in_sizes, int n_in,
                              void* d_out, int out_size)
{
    const float* x   = (const float*)d_in[0];
    const float* xc  = (const float*)d_in[1];
    const float* W1  = (const float*)d_in[2];
    const float* b1  = (const float*)d_in[3];
    const float* g1  = (const float*)d_in[4];
    const float* bt1 = (const float*)d_in[5];
    const float* m1  = (const float*)d_in[6];
    const float* v1  = (const float*)d_in[7];
    const float* W2  = (const float*)d_in[8];
    const float* b2  = (const float*)d_in[9];
    const float* g2  = (const float*)d_in[10];
    const float* bt2 = (const float*)d_in[11];
    const float* m2  = (const float*)d_in[12];
    const float* v2  = (const float*)d_in[13];
    const float* W3  = (const float*)d_in[14];
    const float* b3  = (const float*)d_in[15];
    const float* g3  = (const float*)d_in[16];
    const float* bt3 = (const float*)d_in[17];
    const float* m3  = (const float*)d_in[18];
    const float* v3  = (const float*)d_in[19];
    float* out = (float*)d_out;

    fold_kernel<<<1, 256>>>(W1,b1,g1,bt1,m1,v1, W2,b2,g2,bt2,m2,v2, W3,b3,g3,bt3,m3,v3);
    sort_kernel<<<Bb, 1024>>>(x);

    cudaFuncSetAttribute(pipe_kernel, cudaFuncAttributeMaxDynamicSharedMemorySize, SMEM_BYTES);
    pipe_kernel<<<GRID, TPB, SMEM_BYTES>>>(x, xc, out);
}

// round 13
// speedup vs baseline: 1.3440x; 1.3440x over previous
#include <cuda_runtime.h>
#include <math.h>
#include <float.h>
#include <stdint.h>

#define Bb 4
#define Nn 8192
#define Ss 2048
#define Kk 64
#define EPSf 1e-5f

#define FCTAS 4                  // 1 FPS CTA per batch
#define WCTAS 144                // persistent worker CTAs
#define GRID  (FCTAS + WCTAS)    // 148 CTAs = 1/SM, single wave
#define TPB   512
#define NT    ((Bb*Ss)/4)        // worker tasks (4 centroids each)

typedef unsigned long long ull;

// ---------------- device scratch ----------------
__device__ float g_cen[Bb*Ss*3];
__device__ int   g_prog[Bb];
__device__ float g_sx[Bb*Nn];    // spatially sorted coords
__device__ float g_sy[Bb*Nn];
__device__ float g_sz[Bb*Nn];

// ---------------- packed f32x2 helpers (per-lane rn == scalar rn) ----------------
__device__ __forceinline__ ull pk2(float lo, float hi) {
    ull r; asm("mov.b64 %0, {%1, %2};" : "=l"(r) : "f"(lo), "f"(hi)); return r;
}
__device__ __forceinline__ void up2(ull v, float& a, float& b) {
    asm("mov.b64 {%0, %1}, %2;" : "=f"(a), "=f"(b) : "l"(v));
}
__device__ __forceinline__ ull add2(ull a, ull b) {
    ull r; asm("add.rn.f32x2 %0, %1, %2;" : "=l"(r) : "l"(a), "l"(b)); return r;
}
__device__ __forceinline__ ull mul2(ull a, ull b) {
    ull r; asm("mul.rn.f32x2 %0, %1, %2;" : "=l"(r) : "l"(a), "l"(b)); return r;
}

__device__ __forceinline__ int ld_acquire_gpu(const int* p) {
    int v; asm volatile("ld.acquire.gpu.global.s32 %0, [%1];" : "=r"(v) : "l"(p) : "memory");
    return v;
}
__device__ __forceinline__ void st_release_gpu(int* p, int v) {
    asm volatile("st.release.gpu.global.s32 [%0], %1;" :: "l"(p), "r"(v) : "memory");
}

// weight pointers, passed by value
struct WPtrs {
    const float *W1, *b1, *g1, *bt1, *m1, *v1;
    const float *W2, *b2, *g2, *bt2, *m2, *v2;
    const float *W3, *b3, *g3, *bt3, *m3, *v3;
};

// ---------------- spatial counting sort (Morton 8x8x8) + g_prog reset ----------------
__global__ void __launch_bounds__(1024) sort_kernel(const float* __restrict__ x)
{
    __shared__ int cnt[512];
    __shared__ int psum[512];
    const int b = blockIdx.x;
    const int tid = threadIdx.x;
    const float* xb = x + (size_t)b * Nn * 3;

    if (tid == 0) g_prog[b] = 0;
    if (tid < 512) cnt[tid] = 0;
    __syncthreads();

    int cid[8];
#pragma unroll
    for (int j = 0; j < 8; j++) {
        int p = tid * 8 + j;
        float px = xb[p*3 + 0], py = xb[p*3 + 1], pz = xb[p*3 + 2];
        int ix = min(7, max(0, (int)(px * 8.0f)));
        int iy = min(7, max(0, (int)(py * 8.0f)));
        int iz = min(7, max(0, (int)(pz * 8.0f)));
        int m = (ix & 1) | ((iy & 1) << 1) | ((iz & 1) << 2)
              | ((ix & 2) << 2) | ((iy & 2) << 3) | ((iz & 2) << 4)
              | ((ix & 4) << 4) | ((iy & 4) << 5) | ((iz & 4) << 6);
        cid[j] = m;
        atomicAdd(&cnt[m], 1);
    }
    __syncthreads();
    // Hillis-Steele exclusive scan over 512 counts
    if (tid < 512) psum[tid] = cnt[tid];
    __syncthreads();
    for (int off = 1; off < 512; off <<= 1) {
        int v = 0;
        if (tid < 512 && tid >= off) v = psum[tid - off];
        __syncthreads();
        if (tid < 512 && tid >= off) psum[tid] += v;
        __syncthreads();
    }
    // exclusive base = inclusive - own
    if (tid < 512) { psum[tid] -= cnt[tid]; cnt[tid] = 0; }
    __syncthreads();
#pragma unroll
    for (int j = 0; j < 8; j++) {
        int p = tid * 8 + j;
        int pos = psum[cid[j]] + atomicAdd(&cnt[cid[j]], 1);
        g_sx[b*Nn + pos] = xb[p*3 + 0];
        g_sy[b*Nn + pos] = xb[p*3 + 1];
        g_sz[b*Nn + pos] = xb[p*3 + 2];
    }
}

// ---------------- shared-memory layout (floats) : worker view ----------------
#define OW1 0
#define OB1 (OW1 + 64*67)
#define OW2 (OB1 + 64)
#define OB2 (OW2 + 64*65)
#define OW3 (OB2 + 64)
#define OB3 (OW3 + 128*65)
#define OBUF (OB3 + 128)
#define GRP  (67*65 + 64*65)
#define OIDXA (OBUF + 4*GRP)
#define SMEM_FLOATS (OIDXA + 4*64)
#define SMEM_BYTES  (SMEM_FLOATS * 4)
// fps view (same dynamic buffer): sorted coords + packed combine slots
#define F_SX   0
#define F_SY   Nn
#define F_SZ   (2*Nn)
#define F_KEY  (3*Nn)            // [2][16] u64 (parity-buffered packed {val,idx})

// =====================================================================
// persistent kernel, single launch (512 threads everywhere):
//   CTA 0..3   : FPS, 512 thr x 16 pts, exact pruning, 16-warp barrier
//   CTA 4..147 : workers (4 x 128-thread groups), consume via g_prog
// =====================================================================
__global__ void __launch_bounds__(TPB, 1)
pipe_kernel(const float* __restrict__ x, const float* __restrict__ xc,
            float* __restrict__ out, WPtrs w)
{
    extern __shared__ float sm[];
    const int tid  = threadIdx.x;
    const int lane = tid & 31;
    const int wrp  = tid >> 5;

    if (blockIdx.x < FCTAS) {
        // ================= FPS (512 threads, 16 sorted pts/thread) =================
        const int b = blockIdx.x;

        float* sxs = sm + F_SX;
        float* sys = sm + F_SY;
        float* szs = sm + F_SZ;
        ull* skeyA = (ull*)(sm + F_KEY);    // [2][16]

        for (int i = tid; i < Nn; i += TPB) {
            sxs[i] = g_sx[b*Nn + i];
            sys[i] = g_sy[b*Nn + i];
            szs[i] = g_sz[b*Nn + i];
        }

        // 16 sorted points per thread (8 packed pairs); static reg indexing only
        ull px[8], py[8], pz[8];
        float dist[16];
#pragma unroll
        for (int i = 0; i < 8; i++) {
            int p = b*Nn + tid * 16 + i * 2;
            px[i] = pk2(g_sx[p], g_sx[p+1]);
            py[i] = pk2(g_sy[p], g_sy[p+1]);
            pz[i] = pk2(g_sz[p], g_sz[p+1]);
        }
#pragma unroll
        for (int j = 0; j < 16; j++) dist[j] = 1e10f;

        // per-thread bounding ball (m, rr) over its 16 points (conservative fp)
        float mx = 0.f, my = 0.f, mz = 0.f;
#pragma unroll
        for (int i = 0; i < 8; i++) {
            float a0, a1;
            up2(px[i], a0, a1); mx += a0 + a1;
            up2(py[i], a0, a1); my += a0 + a1;
            up2(pz[i], a0, a1); mz += a0 + a1;
        }
        mx *= 0.0625f; my *= 0.0625f; mz *= 0.0625f;
        float r2 = 0.f;
#pragma unroll
        for (int i = 0; i < 8; i++) {
            float a0, a1, b0, b1, c0, c1;
            up2(px[i], a0, a1); up2(py[i], b0, b1); up2(pz[i], c0, c1);
            float dx0 = a0 - mx, dy0 = b0 - my, dz0 = c0 - mz;
            float dx1 = a1 - mx, dy1 = b1 - my, dz1 = c1 - mz;
            r2 = fmaxf(r2, dx0*dx0 + dy0*dy0 + dz0*dz0);
            r2 = fmaxf(r2, dx1*dx1 + dy1*dy1 + dz1*dz1);
        }
        const float rr = __fsqrt_rn(r2) * 1.0002f + 1e-7f;

        float T  = 3.0e38f;      // prune threshold (forces full path initially)
        float bv = 0.f;          // cached per-thread max dist
        int   bj = 0;            // cached per-thread best local j (0..15)

        // initial centroid = ORIGINAL point 0's coords
        const float* xb0 = x + (size_t)b * Nn * 3;
        float cx = xb0[0], cy = xb0[1], cz = xb0[2];

        int* progp = &g_prog[b];
        __syncthreads();   // staging done

        for (int s = 0; s < Ss; s++) {
            const int par = s & 1;
            if (tid == 0) {
                int oc = (b*Ss + s) * 3;
                g_cen[oc+0] = cx; g_cen[oc+1] = cy; g_cen[oc+2] = cz;
                out[oc+0]  = cx; out[oc+1]  = cy; out[oc+2]  = cz;
                if ((s & 7) == 7) st_release_gpu(progp, s + 1);
            }

            // exact prune: |c-m| >= rr + sqrt(bv) (with margins) -> no update possible
            float ex = cx - mx, ey = cy - my, ez = cz - mz;
            float s2 = fmaf(ez, ez, fmaf(ey, ey, ex*ex));
            bool fullp = s2 < T;
            if (__any_sync(0xffffffffu, fullp)) {
                if (fullp) {
                    const ull ncx = pk2(-cx, -cx);
                    const ull ncy = pk2(-cy, -cy);
                    const ull ncz = pk2(-cz, -cz);
                    float nbv = -1.0f;
                    int   nbj = 0;
#pragma unroll
                    for (int i = 0; i < 8; i++) {
                        ull dx = add2(px[i], ncx);
                        ull dy = add2(py[i], ncy);
                        ull dz = add2(pz[i], ncz);
                        ull dd = add2(add2(mul2(dx,dx), mul2(dy,dy)), mul2(dz,dz));
                        float d0, d1; up2(dd, d0, d1);
                        float n0 = fminf(dist[2*i],   d0);
                        float n1 = fminf(dist[2*i+1], d1);
                        dist[2*i] = n0; dist[2*i+1] = n1;
                        float vp = fmaxf(n0, n1);
                        int   jp = (n0 >= n1) ? (2*i) : (2*i + 1);  // tie -> lower j
                        if (vp > nbv) { nbv = vp; nbj = jp; }       // strict > keeps lower j
                    }
                    bv = nbv; bj = nbj;
                    float sq = __fsqrt_rn(bv) * 1.0001f;
                    float t0 = (rr + sq) * 1.0001f;
                    T = t0 * t0;
                }
            }

            // warp combine: max value, then min sorted index on ties
            unsigned mv   = __float_as_uint(bv);
            unsigned wmax = __reduce_max_sync(0xffffffffu, mv);
            unsigned cand = (mv == wmax) ? (unsigned)(tid*16 + bj) : 0xffffffffu;
            unsigned wmi  = __reduce_min_sync(0xffffffffu, cand);

            // one packed STS.64 per warp
            if (lane == 0)
                skeyA[par*16 + wrp] = ((ull)wmax << 32) | (ull)wmi;
            __syncthreads();   // single 16-warp barrier per step

            // every warp redundantly reduces the 16 warp results
            ull k = (lane < 16) ? skeyA[par*16 + lane] : 0ull;
            unsigned v  = (unsigned)(k >> 32);
            unsigned id = (lane < 16) ? (unsigned)k : 0xffffffffu;
            unsigned M  = __reduce_max_sync(0xffffffffu, v);
            unsigned cn = (v == M) ? id : 0xffffffffu;
            int cur = (int)__reduce_min_sync(0xffffffffu, cn);   // sorted index
            cx = sxs[cur]; cy = sys[cur]; cz = szs[cur];
        }
        return;
    }

    // ================= persistent worker: ball query + MLP (512 thr) =================
    const int widx_ = blockIdx.x - FCTAS;

    // stage FOLDED weights, computed directly from raw inputs (bit-identical to
    // the old fold_kernel expressions) — hidden under FPS runtime
    for (int i = tid; i < 64*67; i += TPB) {
        int o = i / 67;
        sm[OW1 + i] = w.W1[i] * (w.g1[o] * rsqrtf(w.v1[o] + EPSf));
    }
    for (int i = tid; i < 64*64; i += TPB) {
        int o = i >> 6, c = i & 63;
        sm[OW2 + o*65 + c] = w.W2[i] * (w.g2[o] * rsqrtf(w.v2[o] + EPSf));
    }
    for (int i = tid; i < 128*64; i += TPB) {
        int o = i >> 6, c = i & 63;
        sm[OW3 + o*65 + c] = w.W3[i] * (w.g3[o] * rsqrtf(w.v3[o] + EPSf));
    }
    for (int i = tid; i < 64; i += TPB) {
        sm[OB1 + i] = (w.b1[i] - w.m1[i]) * (w.g1[i] * rsqrtf(w.v1[i] + EPSf)) + w.bt1[i];
        sm[OB2 + i] = (w.b2[i] - w.m2[i]) * (w.g2[i] * rsqrtf(w.v2[i] + EPSf)) + w.bt2[i];
    }
    for (int i = tid; i < 128; i += TPB)
        sm[OB3 + i] = (w.b3[i] - w.m3[i]) * (w.g3[i] * rsqrtf(w.v3[i] + EPSf)) + w.bt3[i];

    float* pooled = out + (size_t)Bb * Ss * 3;

    // 4 warpgroups of 128 threads; one centroid per group
    const int wgid    = tid >> 7;        // 0..3
    const int wg_tid  = tid & 127;
    const int tx      = wg_tid & 15;     // 4 k-cols each
    const int ty      = wg_tid >> 4;     // 8 out-rows each (0..7)
    const int wg_warp = (tid >> 5) & 3;

    for (int t = widx_; t < NT; t += WCTAS) {
        const int b  = t & 3;
        const int s0 = (t >> 2) * 4;

        if (tid == 0) {
            while (ld_acquire_gpu(&g_prog[b]) < s0 + 4) __nanosleep(128);
        }
        __syncthreads();   // progress visible + previous task's buffers free

        // ---- ball query: warps 0..3, one centroid each ----
        if (wrp < 4) {
            const int cen = b * Ss + s0 + wrp;
            const float cx = g_cen[cen*3 + 0];
            const float cy = g_cen[cen*3 + 1];
            const float cz = g_cen[cen*3 + 2];
            const float* xb = x + (size_t)b * Nn * 3;
            int* outp = (int*)&sm[OIDXA + wrp*64];

            int count = 0;
            for (int base = 0; base < Nn && count < Kk; base += 32) {
                int p = base + lane;
                float qx = xb[p*3 + 0], qy = xb[p*3 + 1], qz = xb[p*3 + 2];
                float dx = __fsub_rn(cx, qx);
                float dy = __fsub_rn(cy, qy);
                float dz = __fsub_rn(cz, qz);
                float d  = __fadd_rn(__fadd_rn(__fmul_rn(dx,dx), __fmul_rn(dy,dy)),
                                     __fmul_rn(dz,dz));
                bool hit = d < 0.04f;
                unsigned m = __ballot_sync(0xffffffffu, hit);
                int rk = __popc(m & ((1u << lane) - 1u));
                if (hit && (count + rk) < Kk) outp[count + rk] = p;
                count += __popc(m);
            }
            count = min(count, Kk);
            for (int q = count + lane; q < Kk; q += 32) outp[q] = -1;
        }
        __syncthreads();

        const int cen = b * Ss + s0 + wgid;
        const int OF = OBUF + wgid * GRP;   // F [67][65]
        const int OH = OF + 67*65;          // H [64][65]
        int* sidx = (int*)&sm[OIDXA + wgid*64];

        // ---- gather: 4 warps per group, 16 ks per warp ----
        const float* xcb = xc + (size_t)b * Nn * 64;
        const float* xb  = x  + (size_t)b * Nn * 3;
        for (int kk = 0; kk < 16; kk++) {
            int k  = wg_warp * 16 + kk;
            int gi = sidx[k];
            gi = gi < 0 ? 0 : gi;
            const float* row = xcb + (size_t)gi * 64;
            sm[OF + lane*65 + k]      = row[lane];
            sm[OF + (lane+32)*65 + k] = row[lane + 32];
            if (lane < 3)
                sm[OF + (64+lane)*65 + k] = xb[gi*3 + lane] - g_cen[cen*3 + lane];
        }
        __syncthreads();

        float acc[8][4];

        // ---- layer 1: H = relu(W1f @ F + b1f) ----
#pragma unroll
        for (int i = 0; i < 8; i++)
#pragma unroll
            for (int j = 0; j < 4; j++) acc[i][j] = 0.f;
        for (int c = 0; c < 67; c++) {
            float fv[4];
#pragma unroll
            for (int j = 0; j < 4; j++) fv[j] = sm[OF + c*65 + tx*4 + j];
#pragma unroll
            for (int i = 0; i < 8; i++) {
                float wv = sm[OW1 + (ty*8 + i)*67 + c];
#pragma unroll
                for (int j = 0; j < 4; j++) acc[i][j] = fmaf(wv, fv[j], acc[i][j]);
            }
        }
#pragma unroll
        for (int i = 0; i < 8; i++) {
            float bia = sm[OB1 + ty*8 + i];
#pragma unroll
            for (int j = 0; j < 4; j++)
                sm[OH + (ty*8 + i)*65 + tx*4 + j] = fmaxf(acc[i][j] + bia, 0.f);
        }
        __syncthreads();

        // ---- layer 2 (into F buffer) ----
#pragma unroll
        for (int i = 0; i < 8; i++)
#pragma unroll
            for (int j = 0; j < 4; j++) acc[i][j] = 0.f;
        for (int c = 0; c < 64; c++) {
            float fv[4];
#pragma unroll
            for (int j = 0; j < 4; j++) fv[j] = sm[OH + c*65 + tx*4 + j];
#pragma unroll
            for (int i = 0; i < 8; i++) {
                float wv = sm[OW2 + (ty*8 + i)*65 + c];
#pragma unroll
                for (int j = 0; j < 4; j++) acc[i][j] = fmaf(wv, fv[j], acc[i][j]);
            }
        }
#pragma unroll
        for (int i = 0; i < 8; i++) {
            float bia = sm[OB2 + ty*8 + i];
#pragma unroll
            for (int j = 0; j < 4; j++)
                sm[OF + (ty*8 + i)*65 + tx*4 + j] = fmaxf(acc[i][j] + bia, 0.f);
        }
        __syncthreads();

        // ---- layer 3 (128 outs, two 64-row passes) + masked maxpool ----
        for (int op = 0; op < 2; op++) {
#pragma unroll
            for (int i = 0; i < 8; i++)
#pragma unroll
                for (int j = 0; j < 4; j++) acc[i][j] = 0.f;
            for (int c = 0; c < 64; c++) {
                float fv[4];
#pragma unroll
                for (int j = 0; j < 4; j++) fv[j] = sm[OF + c*65 + tx*4 + j];
#pragma unroll
                for (int i = 0; i < 8; i++) {
                    float wv = sm[OW3 + (op*64 + ty*8 + i)*65 + c];
#pragma unroll
                    for (int j = 0; j < 4; j++) acc[i][j] = fmaf(wv, fv[j], acc[i][j]);
                }
            }
#pragma unroll
            for (int i = 0; i < 8; i++) {
                int o = op*64 + ty*8 + i;
                float bia = sm[OB3 + o];
                float m = -INFINITY;
#pragma unroll
                for (int j = 0; j < 4; j++) {
                    int k = tx*4 + j;
                    float v = fmaxf(acc[i][j] + bia, 0.f);
                    if (sidx[k] >= 0) m = fmaxf(m, v);
                }
                // reduce across the 16 tx threads (contiguous 16-lane groups)
#pragma unroll
                for (int off = 8; off; off >>= 1)
                    m = fmaxf(m, __shfl_xor_sync(0xffffffffu, m, off, 16));
                if (tx == 0) pooled[(size_t)cen * 128 + o] = m;
            }
        }
    }
}

// ---------------- launch ----------------
extern "C" void kernel_launch(void* const* d_in, const int* in_sizes, int n_in,
                              void* d_out, int out_size)
{
    const float* x   = (const float*)d_in[0];
    const float* xc  = (const float*)d_in[1];
    WPtrs w;
    w.W1  = (const float*)d_in[2];
    w.b1  = (const float*)d_in[3];
    w.g1  = (const float*)d_in[4];
    w.bt1 = (const float*)d_in[5];
    w.m1  = (const float*)d_in[6];
    w.v1  = (const float*)d_in[7];
    w.W2  = (const float*)d_in[8];
    w.b2  = (const float*)d_in[9];
    w.g2  = (const float*)d_in[10];
    w.bt2 = (const float*)d_in[11];
    w.m2  = (const float*)d_in[12];
    w.v2  = (const float*)d_in[13];
    w.W3  = (const float*)d_in[14];
    w.b3  = (const float*)d_in[15];
    w.g3  = (const float*)d_in[16];
    w.bt3 = (const float*)d_in[17];
    w.m3  = (const float*)d_in[18];
    w.v3  = (const float*)d_in[19];
    float* out = (float*)d_out;

    sort_kernel<<<Bb, 1024>>>(x);

    cudaFuncSetAttribute(pipe_kernel, cudaFuncAttributeMaxDynamicSharedMemorySize, SMEM_BYTES);
    pipe_kernel<<<GRID, TPB, SMEM_BYTES>>>(x, xc, out, w);
}